// round 6
// baseline (speedup 1.0000x reference)
#include <cuda_runtime.h>
#include <cuda_bf16.h>
#include <cstdint>

#define HD 128
#define NT 512
#define MT 64

// byte offsets in the 1024-aligned dynamic smem region
#define OFF_AVH 0u
#define OFF_AVM 16384u
#define OFF_AVL 32768u
#define OFF_ADH 49152u
#define OFF_ADL 65536u
#define OFF_BH  81920u
#define OFF_BM  114688u
#define OFF_BL  147456u
#define OFF_MISC 180224u
#define MAIN_SMEM (180224 + 8192 + 1024)

__device__ float2 g_head[3][2];

// ---------------------------------------------------------------------------
// bf16 split helpers (round-to-nearest splits)
// ---------------------------------------------------------------------------
__device__ __forceinline__ float bf_rn(float x, uint32_t& bits) {
    __nv_bfloat16 b = __float2bfloat16(x);
    bits = (uint32_t)__bfloat16_as_ushort(b);
    return __bfloat162float(b);
}
// 3-way split of a pair -> packed bf16x2 words (elem a in low half)
__device__ __forceinline__ void split3_pair(float a, float b,
                                            uint32_t& h, uint32_t& m, uint32_t& l) {
    uint32_t ha, ma, la, hb, mb, lb;
    float f = bf_rn(a, ha); float r1 = a - f;
    f = bf_rn(r1, ma);      float r2 = r1 - f;
    bf_rn(r2, la);
    f = bf_rn(b, hb);       r1 = b - f;
    f = bf_rn(r1, mb);      r2 = r1 - f;
    bf_rn(r2, lb);
    h = ha | (hb << 16); m = ma | (mb << 16); l = la | (lb << 16);
}
// 2-way split of a pair
__device__ __forceinline__ void split2_pair(float a, float b,
                                            uint32_t& h, uint32_t& l) {
    uint32_t ha, la, hb, lb;
    float f = bf_rn(a, ha); bf_rn(a - f, la);
    f = bf_rn(b, hb);       bf_rn(b - f, lb);
    h = ha | (hb << 16); l = la | (lb << 16);
}

// swizzled byte offset inside a [rows x 128 bf16] tile: row stride 256B,
// 16B chunks XOR-swizzled by row&7 -> conflict-free ldmatrix / STS
__device__ __forceinline__ uint32_t swz8(int row, int col8) {
    return (uint32_t)(row * 256) + ((uint32_t)((col8 ^ (row & 7))) << 4);
}

// ---------------------------------------------------------------------------
// ldmatrix / mma wrappers (baseline PTX, compute_103-safe)
// ---------------------------------------------------------------------------
__device__ __forceinline__ void ldmA(uint32_t f[4], uint32_t base, int r0, int ch, int lane) {
    int g = lane >> 3, i = lane & 7;
    int row = r0 + i + ((g & 1) << 3);
    int c   = ch + (g >> 1);
    uint32_t addr = base + swz8(row, c);
    asm volatile("ldmatrix.sync.aligned.m8n8.x4.shared.b16 {%0,%1,%2,%3}, [%4];"
                 : "=r"(f[0]), "=r"(f[1]), "=r"(f[2]), "=r"(f[3]) : "r"(addr));
}
__device__ __forceinline__ void ldmB(uint32_t f[4], uint32_t base, int n0, int ch, int lane) {
    int g = lane >> 3, i = lane & 7;
    int row = n0 + i + ((g >> 1) << 3);
    int c   = ch + (g & 1);
    uint32_t addr = base + swz8(row, c);
    asm volatile("ldmatrix.sync.aligned.m8n8.x4.shared.b16 {%0,%1,%2,%3}, [%4];"
                 : "=r"(f[0]), "=r"(f[1]), "=r"(f[2]), "=r"(f[3]) : "r"(addr));
}
__device__ __forceinline__ void mma16816(float c[4], const uint32_t a[4],
                                         uint32_t b0, uint32_t b1) {
    asm volatile("mma.sync.aligned.m16n8k16.row.col.f32.bf16.bf16.f32 "
                 "{%0,%1,%2,%3}, {%4,%5,%6,%7}, {%8,%9}, {%0,%1,%2,%3};"
                 : "+f"(c[0]), "+f"(c[1]), "+f"(c[2]), "+f"(c[3])
                 : "r"(a[0]), "r"(a[1]), "r"(a[2]), "r"(a[3]), "r"(b0), "r"(b1));
}
// one A-buffer contribution for current ks against preloaded B frags
__device__ __forceinline__ void mma_a(uint32_t Abase, int m0, int ch, int lane,
                                      const uint32_t bq[2][4], float (*acc)[4]) {
    uint32_t a[4];
    ldmA(a, Abase, m0, ch, lane);
    #pragma unroll
    for (int nt = 0; nt < 4; ++nt)
        mma16816(acc[nt], a, bq[nt >> 1][(nt & 1) * 2], bq[nt >> 1][(nt & 1) * 2 + 1]);
}

// stage W (128x128 fp32) into BH/BM/BL swizzled bf16 split tiles
__device__ __forceinline__ void stage_B(const float* __restrict__ W,
                                        char* __restrict__ smA, int tid) {
    #pragma unroll
    for (int i = 0; i < 4; ++i) {
        int g = tid + i * NT;          // 0..2047
        int j = g >> 4;
        int kg = (g & 15) * 8;
        float4 w0 = *(const float4*)(W + j * HD + kg);
        float4 w1 = *(const float4*)(W + j * HD + kg + 4);
        uint4 h, m, l;
        split3_pair(w0.x, w0.y, h.x, m.x, l.x);
        split3_pair(w0.z, w0.w, h.y, m.y, l.y);
        split3_pair(w1.x, w1.y, h.z, m.z, l.z);
        split3_pair(w1.z, w1.w, h.w, m.w, l.w);
        uint32_t ao = swz8(j, kg >> 3);
        *(uint4*)(smA + OFF_BH + ao) = h;
        *(uint4*)(smA + OFF_BM + ao) = m;
        *(uint4*)(smA + OFF_BL + ao) = l;
    }
}

// ---------------------------------------------------------------------------
// Head kernel (known-good fp32): (v, dv) at n=0,1 for all branches
// ---------------------------------------------------------------------------
#define HWS 129
__global__ void head_kernel(const float* __restrict__ t,
    const float* __restrict__ W1, const float* __restrict__ b1,
    const float* __restrict__ W2, const float* __restrict__ b2,
    const float* __restrict__ W3, const float* __restrict__ b3,
    const float* __restrict__ W4, const float* __restrict__ b4)
{
    extern __shared__ float hsm[];
    __shared__ float2 A[HD], B[HD];
    __shared__ float2 red[HD];
    const int j = threadIdx.x;
    float tv0 = t[0], tv1 = t[1];

    for (int b = 0; b < 3; ++b) {
        float w1 = W1[b*HD + j];
        float c1 = b1[b*HD + j];
        float c2 = b2[b*HD + j];
        float c3 = b3[b*HD + j];
        float w4 = W4[b*HD + j];
        for (int n = 0; n < 2; ++n) {
            float tn = (n == 0) ? tv0 : tv1;
            float pre = fmaf(tn, w1, c1);
            A[j] = make_float2(fmaxf(pre, 0.f), pre > 0.f ? w1 : 0.f);
            __syncthreads();
            for (int idx = j; idx < HD*HD; idx += HD) {
                int jj = idx >> 7, k = idx & 127;
                hsm[jj*HWS + k] = W2[b*HD*HD + idx];
            }
            __syncthreads();
            {
                float av = 0.f, ad = 0.f;
                #pragma unroll 8
                for (int k = 0; k < HD; ++k) {
                    float w = hsm[j*HWS + k]; float2 h = A[k];
                    av = fmaf(w, h.x, av); ad = fmaf(w, h.y, ad);
                }
                float p = av + c2;
                B[j] = make_float2(fmaxf(p, 0.f), p > 0.f ? ad : 0.f);
            }
            __syncthreads();
            for (int idx = j; idx < HD*HD; idx += HD) {
                int jj = idx >> 7, k = idx & 127;
                hsm[jj*HWS + k] = W3[b*HD*HD + idx];
            }
            __syncthreads();
            {
                float av = 0.f, ad = 0.f;
                #pragma unroll 8
                for (int k = 0; k < HD; ++k) {
                    float w = hsm[j*HWS + k]; float2 h = B[k];
                    av = fmaf(w, h.x, av); ad = fmaf(w, h.y, ad);
                }
                float p = av + c3;
                A[j] = make_float2(fmaxf(p, 0.f), p > 0.f ? ad : 0.f);
            }
            __syncthreads();
            red[j] = make_float2(w4 * A[j].x, w4 * A[j].y);
            __syncthreads();
            for (int s = 64; s > 0; s >>= 1) {
                if (j < s) { red[j].x += red[j+s].x; red[j].y += red[j+s].y; }
                __syncthreads();
            }
            if (j == 0) g_head[b][n] = make_float2(red[0].x + b4[b], red[0].y);
            __syncthreads();
        }
    }
}

// ---------------------------------------------------------------------------
// Main kernel: 64 samples/CTA; value = full 3x3 split (8 passes, split
// accumulators), tangent = 2-way x 3-way (3 passes). Grouped by B operand.
// ---------------------------------------------------------------------------
__global__ __launch_bounds__(NT, 1)
void main_kernel(const float* __restrict__ t,
    const float* __restrict__ W1, const float* __restrict__ b1,
    const float* __restrict__ W2, const float* __restrict__ b2,
    const float* __restrict__ W3, const float* __restrict__ b3,
    const float* __restrict__ W4, const float* __restrict__ b4,
    float* __restrict__ out, int N)
{
    extern __shared__ char smem_raw[];
    const uint32_t sb_raw = (uint32_t)__cvta_generic_to_shared(smem_raw);
    const uint32_t sb = (sb_raw + 1023u) & ~1023u;
    char* smA = smem_raw + (sb - sb_raw);

    const int tid  = threadIdx.x;
    const int lane = tid & 31;
    const int w    = tid >> 5;
    const int m0   = (w >> 2) * 16;     // warp's 16-row slab (M=64)
    const int wn   = w & 3;
    const int n0   = wn * 32;           // warp's 32-col slab

    float*  sW1 = (float*)(smA + OFF_MISC) + 0;
    float*  sC1 = (float*)(smA + OFF_MISC) + 128;
    float*  sB2 = (float*)(smA + OFF_MISC) + 256;
    float*  sB3 = (float*)(smA + OFF_MISC) + 384;
    float*  sW4 = (float*)(smA + OFF_MISC) + 512;
    float*  sT  = (float*)(smA + OFF_MISC) + 640;     // 64 floats
    float2* red = (float2*)(smA + OFF_MISC + 2816);   // [64][4]

    const int base = blockIdx.x * MT;
    if (tid < MT) sT[tid] = t[base + tid];

    const uint32_t AVH = sb + OFF_AVH, AVM = sb + OFF_AVM, AVL = sb + OFF_AVL;
    const uint32_t ADH = sb + OFF_ADH, ADL = sb + OFF_ADL;
    const uint32_t BH  = sb + OFF_BH,  BM  = sb + OFF_BM,  BL  = sb + OFF_BL;

    for (int b = 0; b < 3; ++b) {
        if (tid < HD) {
            sW1[tid] = W1[b*HD + tid];
            sC1[tid] = b1[b*HD + tid];
            sB2[tid] = b2[b*HD + tid];
            sB3[tid] = b3[b*HD + tid];
            sW4[tid] = W4[b*HD + tid];
        }
        stage_B(W2 + b*HD*HD, smA, tid);
        __syncthreads();

        // ---- layer 1: elementwise -> A split buffers ----
        #pragma unroll
        for (int i = 0; i < 2; ++i) {
            int g = tid + i * NT;          // 0..1023
            int r = g >> 4, c0 = (g & 15) * 8;
            float tv = sT[r];
            float hv[8], hd[8];
            #pragma unroll
            for (int q = 0; q < 8; ++q) {
                float wv  = sW1[c0 + q];
                float pre = fmaf(tv, wv, sC1[c0 + q]);
                bool mk = pre > 0.f;
                hv[q] = mk ? pre : 0.f;
                hd[q] = mk ? wv  : 0.f;
            }
            uint4 vh, vm, vl, dh, dl;
            split3_pair(hv[0], hv[1], vh.x, vm.x, vl.x);
            split3_pair(hv[2], hv[3], vh.y, vm.y, vl.y);
            split3_pair(hv[4], hv[5], vh.z, vm.z, vl.z);
            split3_pair(hv[6], hv[7], vh.w, vm.w, vl.w);
            split2_pair(hd[0], hd[1], dh.x, dl.x);
            split2_pair(hd[2], hd[3], dh.y, dl.y);
            split2_pair(hd[4], hd[5], dh.z, dl.z);
            split2_pair(hd[6], hd[7], dh.w, dl.w);
            uint32_t ao = swz8(r, c0 >> 3);
            *(uint4*)(smA + OFF_AVH + ao) = vh;
            *(uint4*)(smA + OFF_AVM + ao) = vm;
            *(uint4*)(smA + OFF_AVL + ao) = vl;
            *(uint4*)(smA + OFF_ADH + ao) = dh;
            *(uint4*)(smA + OFF_ADL + ao) = dl;
        }
        __syncthreads();

        #pragma unroll 1
        for (int layer = 0; layer < 2; ++layer) {
            // accv1: dominant h*H term only (fp32-level rounding);
            // accv2: the 7 small correction terms; accd: tangent.
            float accv1[4][4], accv2[4][4], accd[4][4];
            #pragma unroll
            for (int nt = 0; nt < 4; ++nt)
                #pragma unroll
                for (int q = 0; q < 4; ++q) {
                    accv1[nt][q] = 0.f; accv2[nt][q] = 0.f; accd[nt][q] = 0.f;
                }

            // group BH: AVH->accv1 ; AVM, AVL->accv2 ; ADH, ADL->accd
            #pragma unroll
            for (int ks = 0; ks < 8; ++ks) {
                const int ch = ks * 2;
                uint32_t bq[2][4];
                ldmB(bq[0], BH, n0,      ch, lane);
                ldmB(bq[1], BH, n0 + 16, ch, lane);
                mma_a(AVH, m0, ch, lane, bq, accv1);
                mma_a(AVM, m0, ch, lane, bq, accv2);
                mma_a(AVL, m0, ch, lane, bq, accv2);
                mma_a(ADH, m0, ch, lane, bq, accd);
                mma_a(ADL, m0, ch, lane, bq, accd);
            }
            // group BM: AVH, AVM, AVL -> accv2 ; ADH -> accd
            #pragma unroll
            for (int ks = 0; ks < 8; ++ks) {
                const int ch = ks * 2;
                uint32_t bq[2][4];
                ldmB(bq[0], BM, n0,      ch, lane);
                ldmB(bq[1], BM, n0 + 16, ch, lane);
                mma_a(AVH, m0, ch, lane, bq, accv2);
                mma_a(AVM, m0, ch, lane, bq, accv2);
                mma_a(AVL, m0, ch, lane, bq, accv2);
                mma_a(ADH, m0, ch, lane, bq, accd);
            }
            // group BL: AVH, AVM -> accv2
            #pragma unroll
            for (int ks = 0; ks < 8; ++ks) {
                const int ch = ks * 2;
                uint32_t bq[2][4];
                ldmB(bq[0], BL, n0,      ch, lane);
                ldmB(bq[1], BL, n0 + 16, ch, lane);
                mma_a(AVH, m0, ch, lane, bq, accv2);
                mma_a(AVM, m0, ch, lane, bq, accv2);
            }
            __syncthreads();   // all warps done reading A/B before overwrite

            if (layer == 0) {
                // ---- epilogue 2: bias + relu + resplit -> A buffers; stage W3 ----
                float bb[8];
                #pragma unroll
                for (int nt = 0; nt < 4; ++nt) {
                    int c = n0 + 8*nt + (lane & 3)*2;
                    bb[2*nt] = sB2[c]; bb[2*nt+1] = sB2[c+1];
                }
                #pragma unroll
                for (int h = 0; h < 2; ++h) {
                    int row = m0 + 8*h + (lane >> 2);
                    #pragma unroll
                    for (int nt = 0; nt < 4; ++nt) {
                        int c = n0 + 8*nt + (lane & 3)*2;
                        float p0 = accv1[nt][2*h]   + (accv2[nt][2*h]   + bb[2*nt]);
                        float p1 = accv1[nt][2*h+1] + (accv2[nt][2*h+1] + bb[2*nt+1]);
                        bool q0 = p0 > 0.f, q1 = p1 > 0.f;
                        float v0 = q0 ? p0 : 0.f, v1 = q1 ? p1 : 0.f;
                        float d0 = q0 ? accd[nt][2*h]   : 0.f;
                        float d1 = q1 ? accd[nt][2*h+1] : 0.f;
                        uint32_t vh, vm, vl, dh, dl;
                        split3_pair(v0, v1, vh, vm, vl);
                        split2_pair(d0, d1, dh, dl);
                        uint32_t ao = swz8(row, c >> 3) + ((c & 7) << 1);
                        *(uint32_t*)(smA + OFF_AVH + ao) = vh;
                        *(uint32_t*)(smA + OFF_AVM + ao) = vm;
                        *(uint32_t*)(smA + OFF_AVL + ao) = vl;
                        *(uint32_t*)(smA + OFF_ADH + ao) = dh;
                        *(uint32_t*)(smA + OFF_ADL + ao) = dl;
                    }
                }
                stage_B(W3 + b*HD*HD, smA, tid);
                __syncthreads();
            } else {
                // ---- epilogue 3: bias + relu + dot(w4) + reduce + post ----
                float bb[8], ww[8];
                #pragma unroll
                for (int nt = 0; nt < 4; ++nt) {
                    int c = n0 + 8*nt + (lane & 3)*2;
                    bb[2*nt] = sB3[c]; bb[2*nt+1] = sB3[c+1];
                    ww[2*nt] = sW4[c]; ww[2*nt+1] = sW4[c+1];
                }
                #pragma unroll
                for (int h = 0; h < 2; ++h) {
                    int row = m0 + 8*h + (lane >> 2);
                    float sv = 0.f, sd = 0.f;
                    #pragma unroll
                    for (int nt = 0; nt < 4; ++nt) {
                        float p0 = accv1[nt][2*h]   + (accv2[nt][2*h]   + bb[2*nt]);
                        float p1 = accv1[nt][2*h+1] + (accv2[nt][2*h+1] + bb[2*nt+1]);
                        bool q0 = p0 > 0.f, q1 = p1 > 0.f;
                        sv = fmaf(q0 ? p0 : 0.f, ww[2*nt],   sv);
                        sv = fmaf(q1 ? p1 : 0.f, ww[2*nt+1], sv);
                        sd = fmaf(q0 ? accd[nt][2*h]   : 0.f, ww[2*nt],   sd);
                        sd = fmaf(q1 ? accd[nt][2*h+1] : 0.f, ww[2*nt+1], sd);
                    }
                    sv += __shfl_xor_sync(0xffffffffu, sv, 1);
                    sv += __shfl_xor_sync(0xffffffffu, sv, 2);
                    sd += __shfl_xor_sync(0xffffffffu, sd, 1);
                    sd += __shfl_xor_sync(0xffffffffu, sd, 2);
                    if ((lane & 3) == 0) red[row*4 + wn] = make_float2(sv, sd);
                }
                __syncthreads();

                if (tid < MT) {
                    float2 r0 = red[tid*4+0], r1 = red[tid*4+1],
                           r2 = red[tid*4+2], r3 = red[tid*4+3];
                    float v  = r0.x + r1.x + r2.x + r3.x + b4[b];
                    float dv = r0.y + r1.y + r2.y + r3.y;
                    float2 h0 = g_head[b][0];
                    float2 h1 = g_head[b][1];
                    float s = (b == 1) ? -1.f : 1.f;
                    float d1 = h1.x - h0.x;
                    float sg1 = (d1 > 0.f) ? 1.f : ((d1 < 0.f) ? -1.f : 0.f);
                    float dsign1 = s * sg1 * h1.y;
                    int n = base + tid;
                    float d = v - h0.x;
                    float vv, ds;
                    if (n == 0) {
                        vv = 0.f;
                        ds = (dsign1 >= 0.f) ? fabsf(dv) : -fabsf(dv);
                    } else {
                        float sg = (d > 0.f) ? 1.f : ((d < 0.f) ? -1.f : 0.f);
                        vv = s * fabsf(d);
                        ds = s * sg * dv;
                    }
                    out[b*N + n]       = vv;
                    out[(3 + b)*N + n] = ds;
                }
                __syncthreads();
            }
        }
    }
}

// ---------------------------------------------------------------------------
extern "C" void kernel_launch(void* const* d_in, const int* in_sizes, int n_in,
                              void* d_out, int out_size)
{
    const float* t  = (const float*)d_in[0];
    const float* W1 = (const float*)d_in[1];
    const float* b1 = (const float*)d_in[2];
    const float* W2 = (const float*)d_in[3];
    const float* b2 = (const float*)d_in[4];
    const float* W3 = (const float*)d_in[5];
    const float* b3 = (const float*)d_in[6];
    const float* W4 = (const float*)d_in[7];
    const float* b4 = (const float*)d_in[8];
    float* out = (float*)d_out;
    const int N = in_sizes[0];

    const int HEAD_SMEM = HD * HWS * 4;

    cudaFuncSetAttribute(main_kernel, cudaFuncAttributeMaxDynamicSharedMemorySize, MAIN_SMEM);
    cudaFuncSetAttribute(head_kernel, cudaFuncAttributeMaxDynamicSharedMemorySize, HEAD_SMEM);

    head_kernel<<<1, HD, HEAD_SMEM>>>(t, W1, b1, W2, b2, W3, b3, W4, b4);
    main_kernel<<<N / MT, NT, MAIN_SMEM>>>(t, W1, b1, W2, b2, W3, b3, W4, b4, out, N);
}

// round 7
// speedup vs baseline: 1.3600x; 1.3600x over previous
#include <cuda_runtime.h>
#include <cuda_bf16.h>
#include <cstdint>

#define HD 128
#define NT 512
#define MT 64

// byte offsets in the 1024-aligned dynamic smem region
#define OFF_AVH 0u
#define OFF_AVM 16384u
#define OFF_AVL 32768u
#define OFF_ADH 49152u
#define OFF_ADL 65536u
#define OFF_BH  81920u
#define OFF_BM  114688u
#define OFF_BL  147456u
#define OFF_MISC 180224u
#define MAIN_SMEM (180224 + 8192 + 1024)

__device__ float2 g_head[3][2];
// pre-split swizzled weight tiles: [branch][layer(0=W2,1=W3)][3 split levels * 8192 u32]
__device__ uint32_t g_Bsplit[3][2][3 * 8192];

// ---------------------------------------------------------------------------
// bf16 split helpers (round-to-nearest splits)
// ---------------------------------------------------------------------------
__device__ __forceinline__ float bf_rn(float x, uint32_t& bits) {
    __nv_bfloat16 b = __float2bfloat16(x);
    bits = (uint32_t)__bfloat16_as_ushort(b);
    return __bfloat162float(b);
}
__device__ __forceinline__ void split3_pair(float a, float b,
                                            uint32_t& h, uint32_t& m, uint32_t& l) {
    uint32_t ha, ma, la, hb, mb, lb;
    float f = bf_rn(a, ha); float r1 = a - f;
    f = bf_rn(r1, ma);      float r2 = r1 - f;
    bf_rn(r2, la);
    f = bf_rn(b, hb);       r1 = b - f;
    f = bf_rn(r1, mb);      r2 = r1 - f;
    bf_rn(r2, lb);
    h = ha | (hb << 16); m = ma | (mb << 16); l = la | (lb << 16);
}
__device__ __forceinline__ void split2_pair(float a, float b,
                                            uint32_t& h, uint32_t& l) {
    uint32_t ha, la, hb, lb;
    float f = bf_rn(a, ha); bf_rn(a - f, la);
    f = bf_rn(b, hb);       bf_rn(b - f, lb);
    h = ha | (hb << 16); l = la | (lb << 16);
}

// swizzled byte offset inside a [rows x 128 bf16] tile (row stride 256B)
__device__ __forceinline__ uint32_t swz8(int row, int col8) {
    return (uint32_t)(row * 256) + ((uint32_t)((col8 ^ (row & 7))) << 4);
}

// ---------------------------------------------------------------------------
// ldmatrix / mma wrappers (baseline PTX, compute_103-safe)
// ---------------------------------------------------------------------------
__device__ __forceinline__ void ldmA(uint32_t f[4], uint32_t base, int r0, int ch, int lane) {
    int g = lane >> 3, i = lane & 7;
    int row = r0 + i + ((g & 1) << 3);
    int c   = ch + (g >> 1);
    uint32_t addr = base + swz8(row, c);
    asm volatile("ldmatrix.sync.aligned.m8n8.x4.shared.b16 {%0,%1,%2,%3}, [%4];"
                 : "=r"(f[0]), "=r"(f[1]), "=r"(f[2]), "=r"(f[3]) : "r"(addr));
}
__device__ __forceinline__ void ldmB(uint32_t f[4], uint32_t base, int n0, int ch, int lane) {
    int g = lane >> 3, i = lane & 7;
    int row = n0 + i + ((g >> 1) << 3);
    int c   = ch + (g & 1);
    uint32_t addr = base + swz8(row, c);
    asm volatile("ldmatrix.sync.aligned.m8n8.x4.shared.b16 {%0,%1,%2,%3}, [%4];"
                 : "=r"(f[0]), "=r"(f[1]), "=r"(f[2]), "=r"(f[3]) : "r"(addr));
}
__device__ __forceinline__ void mma16816(float c[4], const uint32_t a[4],
                                         uint32_t b0, uint32_t b1) {
    asm volatile("mma.sync.aligned.m16n8k16.row.col.f32.bf16.bf16.f32 "
                 "{%0,%1,%2,%3}, {%4,%5,%6,%7}, {%8,%9}, {%0,%1,%2,%3};"
                 : "+f"(c[0]), "+f"(c[1]), "+f"(c[2]), "+f"(c[3])
                 : "r"(a[0]), "r"(a[1]), "r"(a[2]), "r"(a[3]), "r"(b0), "r"(b1));
}

// flat copy of the three pre-split W tiles (96KB) GMEM -> SMEM
__device__ __forceinline__ void copy_B(const uint4* __restrict__ src,
                                       char* __restrict__ smA, int tid) {
    uint4* dst = (uint4*)(smA + OFF_BH);
    #pragma unroll
    for (int i = 0; i < 12; ++i)
        dst[tid + i * NT] = src[tid + i * NT];
}

// ---------------------------------------------------------------------------
// Prep kernel: split W2/W3 of every branch into swizzled bf16 H/M/L tiles
// ---------------------------------------------------------------------------
__global__ void prep_kernel(const float* __restrict__ W2,
                            const float* __restrict__ W3)
{
    int b = blockIdx.x >> 1, l = blockIdx.x & 1;
    const float* W = (l ? W3 : W2) + b * HD * HD;
    char* dst = (char*)g_Bsplit[b][l];
    for (int g = threadIdx.x; g < 2048; g += NT) {
        int j = g >> 4;
        int kg = (g & 15) * 8;
        float4 w0 = *(const float4*)(W + j * HD + kg);
        float4 w1 = *(const float4*)(W + j * HD + kg + 4);
        uint4 h, m, lo;
        split3_pair(w0.x, w0.y, h.x, m.x, lo.x);
        split3_pair(w0.z, w0.w, h.y, m.y, lo.y);
        split3_pair(w1.x, w1.y, h.z, m.z, lo.z);
        split3_pair(w1.z, w1.w, h.w, m.w, lo.w);
        uint32_t ao = swz8(j, kg >> 3);
        *(uint4*)(dst + ao)         = h;
        *(uint4*)(dst + 32768 + ao) = m;
        *(uint4*)(dst + 65536 + ao) = lo;
    }
}

// ---------------------------------------------------------------------------
// Head kernel (known-good fp32): (v, dv) at n=0,1 for all branches
// ---------------------------------------------------------------------------
#define HWS 129
__global__ void head_kernel(const float* __restrict__ t,
    const float* __restrict__ W1, const float* __restrict__ b1,
    const float* __restrict__ W2, const float* __restrict__ b2,
    const float* __restrict__ W3, const float* __restrict__ b3,
    const float* __restrict__ W4, const float* __restrict__ b4)
{
    extern __shared__ float hsm[];
    __shared__ float2 A[HD], B[HD];
    __shared__ float2 red[HD];
    const int j = threadIdx.x;
    float tv0 = t[0], tv1 = t[1];

    for (int b = 0; b < 3; ++b) {
        float w1 = W1[b*HD + j];
        float c1 = b1[b*HD + j];
        float c2 = b2[b*HD + j];
        float c3 = b3[b*HD + j];
        float w4 = W4[b*HD + j];
        for (int n = 0; n < 2; ++n) {
            float tn = (n == 0) ? tv0 : tv1;
            float pre = fmaf(tn, w1, c1);
            A[j] = make_float2(fmaxf(pre, 0.f), pre > 0.f ? w1 : 0.f);
            __syncthreads();
            for (int idx = j; idx < HD*HD; idx += HD) {
                int jj = idx >> 7, k = idx & 127;
                hsm[jj*HWS + k] = W2[b*HD*HD + idx];
            }
            __syncthreads();
            {
                float av = 0.f, ad = 0.f;
                #pragma unroll 8
                for (int k = 0; k < HD; ++k) {
                    float w = hsm[j*HWS + k]; float2 h = A[k];
                    av = fmaf(w, h.x, av); ad = fmaf(w, h.y, ad);
                }
                float p = av + c2;
                B[j] = make_float2(fmaxf(p, 0.f), p > 0.f ? ad : 0.f);
            }
            __syncthreads();
            for (int idx = j; idx < HD*HD; idx += HD) {
                int jj = idx >> 7, k = idx & 127;
                hsm[jj*HWS + k] = W3[b*HD*HD + idx];
            }
            __syncthreads();
            {
                float av = 0.f, ad = 0.f;
                #pragma unroll 8
                for (int k = 0; k < HD; ++k) {
                    float w = hsm[j*HWS + k]; float2 h = B[k];
                    av = fmaf(w, h.x, av); ad = fmaf(w, h.y, ad);
                }
                float p = av + c3;
                A[j] = make_float2(fmaxf(p, 0.f), p > 0.f ? ad : 0.f);
            }
            __syncthreads();
            red[j] = make_float2(w4 * A[j].x, w4 * A[j].y);
            __syncthreads();
            for (int s = 64; s > 0; s >>= 1) {
                if (j < s) { red[j].x += red[j+s].x; red[j].y += red[j+s].y; }
                __syncthreads();
            }
            if (j == 0) g_head[b][n] = make_float2(red[0].x + b4[b], red[0].y);
            __syncthreads();
        }
    }
}

// ---------------------------------------------------------------------------
// Main kernel: 64 samples/CTA; value = full 3x3 split (8 passes, split
// accumulators), tangent = 3 passes. Fragment-reuse inner loop.
// ---------------------------------------------------------------------------
__global__ __launch_bounds__(NT, 1)
void main_kernel(const float* __restrict__ t,
    const float* __restrict__ W1, const float* __restrict__ b1,
    const float* __restrict__ b2, const float* __restrict__ b3,
    const float* __restrict__ W4, const float* __restrict__ b4,
    float* __restrict__ out, int N)
{
    extern __shared__ char smem_raw[];
    const uint32_t sb_raw = (uint32_t)__cvta_generic_to_shared(smem_raw);
    const uint32_t sb = (sb_raw + 1023u) & ~1023u;
    char* smA = smem_raw + (sb - sb_raw);

    const int tid  = threadIdx.x;
    const int lane = tid & 31;
    const int w    = tid >> 5;
    const int m0   = (w >> 2) * 16;     // warp's 16-row slab (M=64)
    const int wn   = w & 3;
    const int n0   = wn * 32;           // warp's 32-col slab

    float*  sW1 = (float*)(smA + OFF_MISC) + 0;
    float*  sC1 = (float*)(smA + OFF_MISC) + 128;
    float*  sB2 = (float*)(smA + OFF_MISC) + 256;
    float*  sB3 = (float*)(smA + OFF_MISC) + 384;
    float*  sW4 = (float*)(smA + OFF_MISC) + 512;
    float*  sT  = (float*)(smA + OFF_MISC) + 640;     // 64 floats
    float2* red = (float2*)(smA + OFF_MISC + 2816);   // [64][4]

    const int base = blockIdx.x * MT;
    if (tid < MT) sT[tid] = t[base + tid];

    const uint32_t AVH = sb + OFF_AVH, AVM = sb + OFF_AVM, AVL = sb + OFF_AVL;
    const uint32_t ADH = sb + OFF_ADH, ADL = sb + OFF_ADL;
    const uint32_t BH  = sb + OFF_BH,  BM  = sb + OFF_BM,  BL  = sb + OFF_BL;

    for (int b = 0; b < 3; ++b) {
        if (tid < HD) {
            sW1[tid] = W1[b*HD + tid];
            sC1[tid] = b1[b*HD + tid];
            sB2[tid] = b2[b*HD + tid];
            sB3[tid] = b3[b*HD + tid];
            sW4[tid] = W4[b*HD + tid];
        }
        copy_B((const uint4*)g_Bsplit[b][0], smA, tid);
        __syncthreads();

        // ---- layer 1: elementwise -> A split buffers ----
        #pragma unroll
        for (int i = 0; i < 2; ++i) {
            int g = tid + i * NT;          // 0..1023
            int r = g >> 4, c0 = (g & 15) * 8;
            float tv = sT[r];
            float hv[8], hd[8];
            #pragma unroll
            for (int q = 0; q < 8; ++q) {
                float wv  = sW1[c0 + q];
                float pre = fmaf(tv, wv, sC1[c0 + q]);
                bool mk = pre > 0.f;
                hv[q] = mk ? pre : 0.f;
                hd[q] = mk ? wv  : 0.f;
            }
            uint4 vh, vm, vl, dh, dl;
            split3_pair(hv[0], hv[1], vh.x, vm.x, vl.x);
            split3_pair(hv[2], hv[3], vh.y, vm.y, vl.y);
            split3_pair(hv[4], hv[5], vh.z, vm.z, vl.z);
            split3_pair(hv[6], hv[7], vh.w, vm.w, vl.w);
            split2_pair(hd[0], hd[1], dh.x, dl.x);
            split2_pair(hd[2], hd[3], dh.y, dl.y);
            split2_pair(hd[4], hd[5], dh.z, dl.z);
            split2_pair(hd[6], hd[7], dh.w, dl.w);
            uint32_t ao = swz8(r, c0 >> 3);
            *(uint4*)(smA + OFF_AVH + ao) = vh;
            *(uint4*)(smA + OFF_AVM + ao) = vm;
            *(uint4*)(smA + OFF_AVL + ao) = vl;
            *(uint4*)(smA + OFF_ADH + ao) = dh;
            *(uint4*)(smA + OFF_ADL + ao) = dl;
        }
        __syncthreads();

        #pragma unroll 1
        for (int layer = 0; layer < 2; ++layer) {
            // accv1: dominant h*H; accv2: 7 correction terms; accd: tangent.
            float accv1[4][4], accv2[4][4], accd[4][4];
            #pragma unroll
            for (int nt = 0; nt < 4; ++nt)
                #pragma unroll
                for (int q = 0; q < 4; ++q) {
                    accv1[nt][q] = 0.f; accv2[nt][q] = 0.f; accd[nt][q] = 0.f;
                }

            // fragment-reuse inner loop: 11 LDSM + 44 HMMA per ks
            #pragma unroll
            for (int ks = 0; ks < 8; ++ks) {
                const int ch = ks * 2;
                uint32_t avh[4], avm[4], avl[4], adh[4], adl[4];
                uint32_t bh[2][4], bm[2][4], bl[2][4];
                ldmA(avh, AVH, m0, ch, lane);
                ldmA(avm, AVM, m0, ch, lane);
                ldmA(avl, AVL, m0, ch, lane);
                ldmA(adh, ADH, m0, ch, lane);
                ldmA(adl, ADL, m0, ch, lane);
                ldmB(bh[0], BH, n0, ch, lane); ldmB(bh[1], BH, n0 + 16, ch, lane);
                ldmB(bm[0], BM, n0, ch, lane); ldmB(bm[1], BM, n0 + 16, ch, lane);
                ldmB(bl[0], BL, n0, ch, lane); ldmB(bl[1], BL, n0 + 16, ch, lane);
                #pragma unroll
                for (int nt = 0; nt < 4; ++nt) {
                    uint32_t b0h = bh[nt >> 1][(nt & 1)*2], b1h = bh[nt >> 1][(nt & 1)*2+1];
                    uint32_t b0m = bm[nt >> 1][(nt & 1)*2], b1m = bm[nt >> 1][(nt & 1)*2+1];
                    uint32_t b0l = bl[nt >> 1][(nt & 1)*2], b1l = bl[nt >> 1][(nt & 1)*2+1];
                    mma16816(accv1[nt], avh, b0h, b1h);
                    mma16816(accd[nt],  adh, b0h, b1h);
                    mma16816(accv2[nt], avm, b0h, b1h);
                    mma16816(accd[nt],  adl, b0h, b1h);
                    mma16816(accv2[nt], avl, b0h, b1h);
                    mma16816(accd[nt],  adh, b0m, b1m);
                    mma16816(accv2[nt], avh, b0m, b1m);
                    mma16816(accv2[nt], avm, b0m, b1m);
                    mma16816(accv2[nt], avl, b0m, b1m);
                    mma16816(accv2[nt], avh, b0l, b1l);
                    mma16816(accv2[nt], avm, b0l, b1l);
                }
            }
            __syncthreads();   // all warps done reading A/B before overwrite

            if (layer == 0) {
                // ---- epilogue 2: bias + relu + resplit -> A buffers; copy W3 ----
                float bb[8];
                #pragma unroll
                for (int nt = 0; nt < 4; ++nt) {
                    int c = n0 + 8*nt + (lane & 3)*2;
                    bb[2*nt] = sB2[c]; bb[2*nt+1] = sB2[c+1];
                }
                #pragma unroll
                for (int h = 0; h < 2; ++h) {
                    int row = m0 + 8*h + (lane >> 2);
                    #pragma unroll
                    for (int nt = 0; nt < 4; ++nt) {
                        int c = n0 + 8*nt + (lane & 3)*2;
                        float p0 = accv1[nt][2*h]   + (accv2[nt][2*h]   + bb[2*nt]);
                        float p1 = accv1[nt][2*h+1] + (accv2[nt][2*h+1] + bb[2*nt+1]);
                        bool q0 = p0 > 0.f, q1 = p1 > 0.f;
                        float v0 = q0 ? p0 : 0.f, v1 = q1 ? p1 : 0.f;
                        float d0 = q0 ? accd[nt][2*h]   : 0.f;
                        float d1 = q1 ? accd[nt][2*h+1] : 0.f;
                        uint32_t vh, vm, vl, dh, dl;
                        split3_pair(v0, v1, vh, vm, vl);
                        split2_pair(d0, d1, dh, dl);
                        uint32_t ao = swz8(row, c >> 3) + ((c & 7) << 1);
                        *(uint32_t*)(smA + OFF_AVH + ao) = vh;
                        *(uint32_t*)(smA + OFF_AVM + ao) = vm;
                        *(uint32_t*)(smA + OFF_AVL + ao) = vl;
                        *(uint32_t*)(smA + OFF_ADH + ao) = dh;
                        *(uint32_t*)(smA + OFF_ADL + ao) = dl;
                    }
                }
                copy_B((const uint4*)g_Bsplit[b][1], smA, tid);
                __syncthreads();
            } else {
                // ---- epilogue 3: bias + relu + dot(w4) + reduce + post ----
                float bb[8], ww[8];
                #pragma unroll
                for (int nt = 0; nt < 4; ++nt) {
                    int c = n0 + 8*nt + (lane & 3)*2;
                    bb[2*nt] = sB3[c]; bb[2*nt+1] = sB3[c+1];
                    ww[2*nt] = sW4[c]; ww[2*nt+1] = sW4[c+1];
                }
                #pragma unroll
                for (int h = 0; h < 2; ++h) {
                    int row = m0 + 8*h + (lane >> 2);
                    float sv = 0.f, sd = 0.f;
                    #pragma unroll
                    for (int nt = 0; nt < 4; ++nt) {
                        float p0 = accv1[nt][2*h]   + (accv2[nt][2*h]   + bb[2*nt]);
                        float p1 = accv1[nt][2*h+1] + (accv2[nt][2*h+1] + bb[2*nt+1]);
                        bool q0 = p0 > 0.f, q1 = p1 > 0.f;
                        sv = fmaf(q0 ? p0 : 0.f, ww[2*nt],   sv);
                        sv = fmaf(q1 ? p1 : 0.f, ww[2*nt+1], sv);
                        sd = fmaf(q0 ? accd[nt][2*h]   : 0.f, ww[2*nt],   sd);
                        sd = fmaf(q1 ? accd[nt][2*h+1] : 0.f, ww[2*nt+1], sd);
                    }
                    sv += __shfl_xor_sync(0xffffffffu, sv, 1);
                    sv += __shfl_xor_sync(0xffffffffu, sv, 2);
                    sd += __shfl_xor_sync(0xffffffffu, sd, 1);
                    sd += __shfl_xor_sync(0xffffffffu, sd, 2);
                    if ((lane & 3) == 0) red[row*4 + wn] = make_float2(sv, sd);
                }
                __syncthreads();

                if (tid < MT) {
                    float2 r0 = red[tid*4+0], r1 = red[tid*4+1],
                           r2 = red[tid*4+2], r3 = red[tid*4+3];
                    float v  = r0.x + r1.x + r2.x + r3.x + b4[b];
                    float dv = r0.y + r1.y + r2.y + r3.y;
                    float2 h0 = g_head[b][0];
                    float2 h1 = g_head[b][1];
                    float s = (b == 1) ? -1.f : 1.f;
                    float d1 = h1.x - h0.x;
                    float sg1 = (d1 > 0.f) ? 1.f : ((d1 < 0.f) ? -1.f : 0.f);
                    float dsign1 = s * sg1 * h1.y;
                    int n = base + tid;
                    float d = v - h0.x;
                    float vv, ds;
                    if (n == 0) {
                        vv = 0.f;
                        ds = (dsign1 >= 0.f) ? fabsf(dv) : -fabsf(dv);
                    } else {
                        float sg = (d > 0.f) ? 1.f : ((d < 0.f) ? -1.f : 0.f);
                        vv = s * fabsf(d);
                        ds = s * sg * dv;
                    }
                    out[b*N + n]       = vv;
                    out[(3 + b)*N + n] = ds;
                }
                __syncthreads();
            }
        }
    }
}

// ---------------------------------------------------------------------------
extern "C" void kernel_launch(void* const* d_in, const int* in_sizes, int n_in,
                              void* d_out, int out_size)
{
    const float* t  = (const float*)d_in[0];
    const float* W1 = (const float*)d_in[1];
    const float* b1 = (const float*)d_in[2];
    const float* W2 = (const float*)d_in[3];
    const float* b2 = (const float*)d_in[4];
    const float* W3 = (const float*)d_in[5];
    const float* b3 = (const float*)d_in[6];
    const float* W4 = (const float*)d_in[7];
    const float* b4 = (const float*)d_in[8];
    float* out = (float*)d_out;
    const int N = in_sizes[0];

    const int HEAD_SMEM = HD * HWS * 4;

    cudaFuncSetAttribute(main_kernel, cudaFuncAttributeMaxDynamicSharedMemorySize, MAIN_SMEM);
    cudaFuncSetAttribute(head_kernel, cudaFuncAttributeMaxDynamicSharedMemorySize, HEAD_SMEM);

    prep_kernel<<<6, NT>>>(W2, W3);
    head_kernel<<<1, HD, HEAD_SMEM>>>(t, W1, b1, W2, b2, W3, b3, W4, b4);
    main_kernel<<<N / MT, NT, MAIN_SMEM>>>(t, W1, b1, b2, b3, W4, b4, out, N);
}